// round 9
// baseline (speedup 1.0000x reference)
#include <cuda_runtime.h>
#include <math.h>

// B = 2048 rows, N = 4095 points/row.
// d_in[0] origin_3D (B,3,1), d_in[1] spherical_3D (B,3,N),
// d_in[2] origin_2D (B,3,1), d_in[3] spherical_2D (B,3,N),
// d_in[4] deformation_field (B,2,N). Output: scalar f32.
//
// diff-of-cumsums == cumsum-of-diffs:
//   carry = origin3 - origin2
//   row = |carry|_1 + sum_j |carry + prefix_j(Delta)|_1 ; row /= (N+1); out = sum rows.

#define NPTS   4095
#define NB     2048
#define BTH    512
#define ITEMS  8                    // 512*8 = 4096 slots
#define PADDED 4224                 // 4096 + 4096/32 pad
#define SMEMB  (3 * PADDED * 4)     // 50688 bytes dynamic smem

__device__ float        g_partials[NB];
__device__ unsigned int g_count = 0;

__global__ void __launch_bounds__(BTH, 4)
mpd_loss_fused(const float* __restrict__ o3,
               const float* __restrict__ s3,
               const float* __restrict__ o2,
               const float* __restrict__ s2,
               const float* __restrict__ df,
               float* __restrict__ out)
{
    extern __shared__ float sm[];
    float* sxm = sm;
    float* sym = sm + PADDED;
    float* szm = sm + 2 * PADDED;

    const int b    = blockIdx.x;
    const int t    = threadIdx.x;
    const int wid  = t >> 5;
    const int lane = t & 31;

    // Single base pointer per tensor; stream offsets become LDG immediates.
    const float* s3row = s3 + (size_t)(b * 3) * NPTS;
    const float* s2row = s2 + (size_t)(b * 3) * NPTS;
    const float* dfrow = df + (size_t)(b * 2) * NPTS;

    // ---- Phase 1: strided coalesced loads + trig; deltas -> padded smem ----
#pragma unroll
    for (int i = 0; i < ITEMS; i++) {
        int j = i * BTH + t;
        float ddx = 0.f, ddy = 0.f, ddz = 0.f;
        if (j < NPTS) {
            float r3 = s3row[j];
            float a3 = s3row[j + NPTS]     + dfrow[j];
            float p3 = s3row[j + 2 * NPTS] + dfrow[j + NPTS];
            float r2 = s2row[j];
            float a2 = s2row[j + NPTS];
            float p2 = s2row[j + 2 * NPTS];
            float st3, ct3, sp3, cp3, st2, ct2, sp2, cp2;
            __sincosf(a3, &st3, &ct3);
            __sincosf(p3, &sp3, &cp3);
            __sincosf(a2, &st2, &ct2);
            __sincosf(p2, &sp2, &cp2);
            float rs3 = r3 * st3;
            float rs2 = r2 * st2;
            ddx = rs3 * cp3 - rs2 * cp2;
            ddy = rs3 * sp3 - rs2 * sp2;
            ddz = r3 * ct3 - r2 * ct2;
        }
        int p = j + (j >> 5);          // pad: conflict-free writes (contiguous per warp)
        sxm[p] = ddx; sym[p] = ddy; szm[p] = ddz;
    }

    float cx = o3[b * 3 + 0] - o2[b * 3 + 0];
    float cy = o3[b * 3 + 1] - o2[b * 3 + 1];
    float cz = o3[b * 3 + 2] - o2[b * 3 + 2];

    __syncthreads();

    // ---- Phase 2: per-thread serial totals over 8 contiguous elems ----
    // element e = 8t+k  ->  padded index 8t + (t>>2) + k   (conflict-free reads)
    const int pb = t * ITEMS + (t >> 2);
    float ax = 0.f, ay = 0.f, az = 0.f;
#pragma unroll
    for (int k = 0; k < ITEMS; k++) {
        ax += sxm[pb + k];
        ay += sym[pb + k];
        az += szm[pb + k];
    }

    // ---- single 512-wide block scan of thread totals ----
    __shared__ float wsx[16], wsy[16], wsz[16];
    float ix = ax, iy = ay, iz = az;        // warp-inclusive scan values
#pragma unroll
    for (int d = 1; d < 32; d <<= 1) {
        float ox = __shfl_up_sync(0xffffffffu, ix, d);
        float oy = __shfl_up_sync(0xffffffffu, iy, d);
        float oz = __shfl_up_sync(0xffffffffu, iz, d);
        if (lane >= d) { ix += ox; iy += oy; iz += oz; }
    }
    if (lane == 31) { wsx[wid] = ix; wsy[wid] = iy; wsz[wid] = iz; }
    __syncthreads();
    if (t < 16) {
        float vx = wsx[t], vy = wsy[t], vz = wsz[t];
#pragma unroll
        for (int d = 1; d < 16; d <<= 1) {
            float ox = __shfl_up_sync(0x0000ffffu, vx, d, 16);
            float oy = __shfl_up_sync(0x0000ffffu, vy, d, 16);
            float oz = __shfl_up_sync(0x0000ffffu, vz, d, 16);
            if (t >= d) { vx += ox; vy += oy; vz += oz; }
        }
        wsx[t] = vx; wsy[t] = vy; wsz[t] = vz;
    }
    __syncthreads();

    // exclusive thread offset + origin carry
    float rx = cx + (wid ? wsx[wid - 1] : 0.f) + (ix - ax);
    float ry = cy + (wid ? wsy[wid - 1] : 0.f) + (iy - ay);
    float rz = cz + (wid ? wsz[wid - 1] : 0.f) + (iz - az);

    // ---- Phase 3: re-read deltas, running prefix + |.|_1 accumulate ----
    float acc = 0.f;
    if (t == 0) acc = fabsf(cx) + fabsf(cy) + fabsf(cz);        // j=0 origin term
#pragma unroll
    for (int k = 0; k < ITEMS; k++) {
        rx += sxm[pb + k];
        ry += sym[pb + k];
        rz += szm[pb + k];
        if (t * ITEMS + k < NPTS)
            acc += fabsf(rx) + fabsf(ry) + fabsf(rz);
    }

    // ---- block reduce acc ----
#pragma unroll
    for (int d = 16; d > 0; d >>= 1)
        acc += __shfl_down_sync(0xffffffffu, acc, d);
    if (lane == 0) wsx[wid] = acc;
    __syncthreads();

    __shared__ bool isLast;
    if (t == 0) {
        float s = 0.f;
#pragma unroll
        for (int k = 0; k < 16; k++) s += wsx[k];
        g_partials[b] = s * (1.0f / (float)(NPTS + 1));
        __threadfence();
        unsigned int c = atomicAdd(&g_count, 1u);
        isLast = (c == NB - 1);
    }
    __syncthreads();

    // ---- fused deterministic final reduction (last block) ----
    if (isLast) {
        float v = g_partials[t] + g_partials[t + 512] +
                  g_partials[t + 1024] + g_partials[t + 1536];
#pragma unroll
        for (int d = 16; d > 0; d >>= 1)
            v += __shfl_down_sync(0xffffffffu, v, d);
        if (lane == 0) wsy[wid] = v;
        __syncthreads();
        if (t == 0) {
            float s = 0.f;
#pragma unroll
            for (int k = 0; k < 16; k++) s += wsy[k];
            out[0] = s;
            g_count = 0;                  // reset for next graph replay
        }
    }
}

extern "C" void kernel_launch(void* const* d_in, const int* in_sizes, int n_in,
                              void* d_out, int out_size)
{
    (void)in_sizes; (void)n_in; (void)out_size;
    const float* o3 = (const float*)d_in[0];
    const float* s3 = (const float*)d_in[1];
    const float* o2 = (const float*)d_in[2];
    const float* s2 = (const float*)d_in[3];
    const float* df = (const float*)d_in[4];
    float* out = (float*)d_out;

    cudaFuncSetAttribute(mpd_loss_fused,
                         cudaFuncAttributeMaxDynamicSharedMemorySize, SMEMB);
    mpd_loss_fused<<<NB, BTH, SMEMB>>>(o3, s3, o2, s2, df, out);
}

// round 13
// speedup vs baseline: 1.1770x; 1.1770x over previous
#include <cuda_runtime.h>
#include <math.h>

// B = 2048 rows, N = 4095 points/row.
// d_in[0] origin_3D (B,3,1), d_in[1] spherical_3D (B,3,N),
// d_in[2] origin_2D (B,3,1), d_in[3] spherical_2D (B,3,N),
// d_in[4] deformation_field (B,2,N). Output: scalar f32.
//
// diff-of-cumsums == cumsum-of-diffs:
//   carry = origin3 - origin2
//   row = |carry|_1 + sum_j |carry + prefix_j(Delta)|_1 ; row /= (N+1); out = sum rows.
//
// Layout: warp w owns contiguous elements [256w, 256w+256); chunk i gives
// j = 256w + 32i + lane (coalesced). Warp-local inclusive scan per chunk with a
// running warp carry -> per-element prefixes stored to smem (lane-consecutive,
// conflict-free, no padding). One block scan over 16 warp totals at the end.

#define NPTS   4095
#define NB     2048
#define BTH    512
#define ITEMS  8                    // 8 chunks of 32 per warp = 256 elems/warp
#define SLOTS  4096
#define SMEMB  (3 * SLOTS * 4)      // 49152 bytes dynamic smem

__device__ float        g_partials[NB];
__device__ unsigned int g_count = 0;

__global__ void __launch_bounds__(BTH, 3)
mpd_loss_fused(const float* __restrict__ o3,
               const float* __restrict__ s3,
               const float* __restrict__ o2,
               const float* __restrict__ s2,
               const float* __restrict__ df,
               float* __restrict__ out)
{
    extern __shared__ float sm[];
    float* sxm = sm;
    float* sym = sm + SLOTS;
    float* szm = sm + 2 * SLOTS;

    const int b    = blockIdx.x;
    const int t    = threadIdx.x;
    const int wid  = t >> 5;
    const int lane = t & 31;

    // Single base pointer per tensor; stream offsets fold into LDG immediates.
    const float* s3row = s3 + (size_t)(b * 3) * NPTS;
    const float* s2row = s2 + (size_t)(b * 3) * NPTS;
    const float* dfrow = df + (size_t)(b * 2) * NPTS;

    // ---- Phase 1: load + trig + fused warp-local scan; prefixes -> smem ----
    float wcx = 0.f, wcy = 0.f, wcz = 0.f;     // running warp carry
#pragma unroll
    for (int i = 0; i < ITEMS; i++) {
        int j = wid * 256 + i * 32 + lane;     // warp-contiguous, coalesced
        float dx = 0.f, dy = 0.f, dz = 0.f;
        if (j < NPTS) {
            float r3 = s3row[j];
            float a3 = s3row[j + NPTS]     + dfrow[j];
            float p3 = s3row[j + 2 * NPTS] + dfrow[j + NPTS];
            float r2 = s2row[j];
            float a2 = s2row[j + NPTS];
            float p2 = s2row[j + 2 * NPTS];
            float st3, ct3, sp3, cp3, st2, ct2, sp2, cp2;
            __sincosf(a3, &st3, &ct3);
            __sincosf(p3, &sp3, &cp3);
            __sincosf(a2, &st2, &ct2);
            __sincosf(p2, &sp2, &cp2);
            float rs3 = r3 * st3;
            float rs2 = r2 * st2;
            dx = rs3 * cp3 - rs2 * cp2;
            dy = rs3 * sp3 - rs2 * sp2;
            dz = r3 * ct3 - r2 * ct2;
        }
        // warp inclusive scan of this 32-chunk
#pragma unroll
        for (int d = 1; d < 32; d <<= 1) {
            float ox = __shfl_up_sync(0xffffffffu, dx, d);
            float oy = __shfl_up_sync(0xffffffffu, dy, d);
            float oz = __shfl_up_sync(0xffffffffu, dz, d);
            if (lane >= d) { dx += ox; dy += oy; dz += oz; }
        }
        sxm[j] = wcx + dx;
        sym[j] = wcy + dy;
        szm[j] = wcz + dz;
        wcx += __shfl_sync(0xffffffffu, dx, 31);   // chunk total
        wcy += __shfl_sync(0xffffffffu, dy, 31);
        wcz += __shfl_sync(0xffffffffu, dz, 31);
    }

    // ---- block scan over the 16 warp totals ----
    __shared__ float wsx[16], wsy[16], wsz[16];
    if (lane == 0) { wsx[wid] = wcx; wsy[wid] = wcy; wsz[wid] = wcz; }
    __syncthreads();
    if (t < 16) {
        float vx = wsx[t], vy = wsy[t], vz = wsz[t];
#pragma unroll
        for (int d = 1; d < 16; d <<= 1) {
            float ox = __shfl_up_sync(0x0000ffffu, vx, d, 16);
            float oy = __shfl_up_sync(0x0000ffffu, vy, d, 16);
            float oz = __shfl_up_sync(0x0000ffffu, vz, d, 16);
            if (t >= d) { vx += ox; vy += oy; vz += oz; }
        }
        wsx[t] = vx; wsy[t] = vy; wsz[t] = vz;
    }
    __syncthreads();

    float cx = o3[b * 3 + 0] - o2[b * 3 + 0];
    float cy = o3[b * 3 + 1] - o2[b * 3 + 1];
    float cz = o3[b * 3 + 2] - o2[b * 3 + 2];

    float offx = cx + (wid ? wsx[wid - 1] : 0.f);   // exclusive warp offset + carry
    float offy = cy + (wid ? wsy[wid - 1] : 0.f);
    float offz = cz + (wid ? wsz[wid - 1] : 0.f);

    // ---- Phase 2: re-read prefixes (lane-consecutive), |.|_1 accumulate ----
    float acc = 0.f;
    if (t == 0) acc = fabsf(cx) + fabsf(cy) + fabsf(cz);       // j=0 origin term
#pragma unroll
    for (int i = 0; i < ITEMS; i++) {
        int j = wid * 256 + i * 32 + lane;
        if (j < NPTS)
            acc += fabsf(sxm[j] + offx) + fabsf(sym[j] + offy) + fabsf(szm[j] + offz);
    }

    // ---- block reduce acc ----
#pragma unroll
    for (int d = 16; d > 0; d >>= 1)
        acc += __shfl_down_sync(0xffffffffu, acc, d);
    if (lane == 0) wsx[wid] = acc;
    __syncthreads();

    __shared__ bool isLast;
    if (t == 0) {
        float s = 0.f;
#pragma unroll
        for (int k = 0; k < 16; k++) s += wsx[k];
        g_partials[b] = s * (1.0f / (float)(NPTS + 1));
        __threadfence();
        unsigned int c = atomicAdd(&g_count, 1u);
        isLast = (c == NB - 1);
    }
    __syncthreads();

    // ---- fused deterministic final reduction (last block) ----
    if (isLast) {
        float v = g_partials[t] + g_partials[t + 512] +
                  g_partials[t + 1024] + g_partials[t + 1536];
#pragma unroll
        for (int d = 16; d > 0; d >>= 1)
            v += __shfl_down_sync(0xffffffffu, v, d);
        if (lane == 0) wsy[wid] = v;
        __syncthreads();
        if (t == 0) {
            float s = 0.f;
#pragma unroll
            for (int k = 0; k < 16; k++) s += wsy[k];
            out[0] = s;
            g_count = 0;                  // reset for next graph replay
        }
    }
}

extern "C" void kernel_launch(void* const* d_in, const int* in_sizes, int n_in,
                              void* d_out, int out_size)
{
    (void)in_sizes; (void)n_in; (void)out_size;
    const float* o3 = (const float*)d_in[0];
    const float* s3 = (const float*)d_in[1];
    const float* o2 = (const float*)d_in[2];
    const float* s2 = (const float*)d_in[3];
    const float* df = (const float*)d_in[4];
    float* out = (float*)d_out;

    cudaFuncSetAttribute(mpd_loss_fused,
                         cudaFuncAttributeMaxDynamicSharedMemorySize, SMEMB);
    mpd_loss_fused<<<NB, BTH, SMEMB>>>(o3, s3, o2, s2, df, out);
}